// round 10
// baseline (speedup 1.0000x reference)
#include <cuda_runtime.h>
#include <cuda_bf16.h>
#include <cstdint>
#include <math.h>

#define BATCH 2
#define TLEN 2048
#define DIM 1024
#define HEADS 16
#define DH 64
#define WINDOW 32
#define NTOK (BATCH * TLEN)
#define LN_EPS 1e-5f

// ---------------- scratch (device globals; same 96 MB set as R8/R9) -------
__device__ float g_h[(size_t)NTOK * DIM];          // LN output, [tok, DIM]
__device__ float g_qkv[(size_t)NTOK * 3 * DIM];    // [tok, 3*DIM]
__device__ float g_att[(size_t)NTOK * DIM];        // attention output, [tok, DIM]
__device__ float g_proj[(size_t)NTOK * DIM];       // out-proj, [tok, DIM]

// ---------------- 1) LayerNorm + transpose [B,C,T] -> [tok,C] -------------
__global__ void ln_transpose_kernel(const float* __restrict__ x,
                                    const float* __restrict__ w,
                                    const float* __restrict__ bias) {
    const int b  = blockIdx.y;
    const int t0 = blockIdx.x * 32;
    const int tx = threadIdx.x, ty = threadIdx.y;
    const float* xb = x + (size_t)b * DIM * TLEN;

    float s = 0.f, ss = 0.f;
    for (int c = ty; c < DIM; c += 8) {
        float v = xb[(size_t)c * TLEN + t0 + tx];
        s += v; ss += v * v;
    }
    __shared__ float rs[8][32], rq[8][32];
    rs[ty][tx] = s; rq[ty][tx] = ss;
    __syncthreads();
    __shared__ float mu[32], rstd[32];
    if (ty == 0) {
        float a = 0.f, q = 0.f;
        #pragma unroll
        for (int i = 0; i < 8; i++) { a += rs[i][tx]; q += rq[i][tx]; }
        float m   = a / (float)DIM;
        float var = q / (float)DIM - m * m;
        mu[tx]   = m;
        rstd[tx] = rsqrtf(var + LN_EPS);
    }
    __syncthreads();

    __shared__ float tile[32][33];
    for (int c0 = 0; c0 < DIM; c0 += 32) {
        #pragma unroll
        for (int k = 0; k < 4; k++) {
            int cl = ty + 8 * k;
            tile[cl][tx] = xb[(size_t)(c0 + cl) * TLEN + t0 + tx];
        }
        __syncthreads();
        #pragma unroll
        for (int k = 0; k < 4; k++) {
            int tl = ty + 8 * k;
            int c  = c0 + tx;
            float v = (tile[tx][tl] - mu[tl]) * rstd[tl] * w[c] + bias[c];
            g_h[((size_t)b * TLEN + t0 + tl) * DIM + c] = v;
        }
        __syncthreads();
    }
}

// ---------------- 2/5) bf16x3 tensor-core GEMM, presplit smem --------------
// C[M,N] = A[M,K] * B[K,N], fp32 global, bf16 hi/lo split at tile load.
// CTA tile 128x64xk32, 8 warps (4m x 2n), warp tile 32x32.
// A smem [m][k] bf16, B smem TRANSPOSED [n][k] bf16 -> all frags = 1 LDS.32.
#define SROWA 40   // bf16 k-stride for A rows
#define SROWB 40   // bf16 k-stride for B rows ([n][k])

#define MMA16816(d, a0, a1, a2, a3, b0, b1)                                   \
    asm volatile("mma.sync.aligned.m16n8k16.row.col.f32.bf16.bf16.f32 "      \
                 "{%0,%1,%2,%3}, {%4,%5,%6,%7}, {%8,%9}, {%0,%1,%2,%3};"     \
                 : "+f"(d[0]), "+f"(d[1]), "+f"(d[2]), "+f"(d[3])             \
                 : "r"(a0), "r"(a1), "r"(a2), "r"(a3), "r"(b0), "r"(b1))

__device__ __forceinline__ void split2(float fx, float fy,
                                       uint32_t& hi, uint32_t& lo) {
    __nv_bfloat162 h = __floats2bfloat162_rn(fx, fy);
    float2 hf = __bfloat1622float2(h);
    __nv_bfloat162 l = __floats2bfloat162_rn(fx - hf.x, fy - hf.y);
    hi = *(uint32_t*)&h;
    lo = *(uint32_t*)&l;
}

__global__ __launch_bounds__(256)
void sgemm_tc_kernel(int which, const float* __restrict__ Bm, int N) {
    const float* __restrict__ A = (which == 0) ? g_h : g_att;
    float* __restrict__ C = (which == 0) ? g_qkv : g_proj;
    const int K = DIM;

    __shared__ __nv_bfloat16 sAhi[128 * SROWA];   // 10240 B
    __shared__ __nv_bfloat16 sAlo[128 * SROWA];
    __shared__ __nv_bfloat16 sBhi[64 * SROWB];    //  5120 B
    __shared__ __nv_bfloat16 sBlo[64 * SROWB];    // total 30720 B

    const int tid  = threadIdx.x;
    const int warp = tid >> 5, lane = tid & 31;
    const int wm0 = (warp & 3) * 32;
    const int wn0 = (warp >> 2) * 32;
    const int m0 = blockIdx.y * 128;
    const int n0 = blockIdx.x * 64;

    float acc[2][4][4];
    #pragma unroll
    for (int i = 0; i < 2; i++)
        #pragma unroll
        for (int j = 0; j < 4; j++)
            #pragma unroll
            for (int k = 0; k < 4; k++) acc[i][j][k] = 0.f;

    const int r  = lane >> 2;
    const int c2 = (lane & 3) * 2;

    // loader mapping: A 4 float4/thread, B 2 float4/thread
    const int ar = tid >> 3;             // 0..31 (+32*i)
    const int ac = (tid & 7) * 4;        // k col 0..28
    const int br = tid >> 4;             // 0..15 (+16*i)  (k row in tile)
    const int bc = (tid & 15) * 4;       // n col 0..60

    float4 pa[4], pb[2];

    #define FETCH(kt)                                                          \
    do {                                                                       \
        int kb = (kt) * 32;                                                    \
        _Pragma("unroll")                                                      \
        for (int i = 0; i < 4; i++)                                            \
            pa[i] = *(const float4*)&A[(size_t)(m0 + ar + 32 * i) * K + kb + ac]; \
        _Pragma("unroll")                                                      \
        for (int i = 0; i < 2; i++)                                            \
            pb[i] = *(const float4*)&Bm[(size_t)(kb + br + 16 * i) * N + n0 + bc]; \
    } while (0)

    // convert + store (A row-major; B transposed to [n][k])
    #define STORE()                                                            \
    do {                                                                       \
        _Pragma("unroll")                                                      \
        for (int i = 0; i < 4; i++) {                                          \
            int row = ar + 32 * i;                                             \
            uint32_t h0, l0, h1, l1;                                           \
            split2(pa[i].x, pa[i].y, h0, l0);                                  \
            split2(pa[i].z, pa[i].w, h1, l1);                                  \
            *(uint2*)&sAhi[row * SROWA + ac] = make_uint2(h0, h1);             \
            *(uint2*)&sAlo[row * SROWA + ac] = make_uint2(l0, l1);             \
        }                                                                      \
        _Pragma("unroll")                                                      \
        for (int i = 0; i < 2; i++) {                                          \
            int krow = br + 16 * i;                                            \
            float vv[4] = {pb[i].x, pb[i].y, pb[i].z, pb[i].w};                \
            _Pragma("unroll")                                                  \
            for (int j = 0; j < 4; j++) {                                      \
                __nv_bfloat16 hb = __float2bfloat16(vv[j]);                    \
                __nv_bfloat16 lb = __float2bfloat16(vv[j] - __bfloat162float(hb)); \
                sBhi[(bc + j) * SROWB + krow] = hb;                            \
                sBlo[(bc + j) * SROWB + krow] = lb;                            \
            }                                                                  \
        }                                                                      \
    } while (0)

    const int ntiles = K / 32;
    FETCH(0);

    for (int kt = 0; kt < ntiles; kt++) {
        STORE();
        __syncthreads();
        if (kt + 1 < ntiles) FETCH(kt + 1);   // overlap next tile's GMEM loads

        #pragma unroll
        for (int ks = 0; ks < 2; ks++) {
            const int kc = ks * 16 + c2;
            uint32_t bh[4][2], bl[4][2];
            #pragma unroll
            for (int nt = 0; nt < 4; nt++) {
                int n = wn0 + nt * 8 + r;
                bh[nt][0] = *(const uint32_t*)&sBhi[n * SROWB + kc];
                bh[nt][1] = *(const uint32_t*)&sBhi[n * SROWB + kc + 8];
                bl[nt][0] = *(const uint32_t*)&sBlo[n * SROWB + kc];
                bl[nt][1] = *(const uint32_t*)&sBlo[n * SROWB + kc + 8];
            }
            #pragma unroll
            for (int mt = 0; mt < 2; mt++) {
                int row = wm0 + mt * 16 + r;
                uint32_t ah0 = *(const uint32_t*)&sAhi[row * SROWA + kc];
                uint32_t ah1 = *(const uint32_t*)&sAhi[(row + 8) * SROWA + kc];
                uint32_t ah2 = *(const uint32_t*)&sAhi[row * SROWA + kc + 8];
                uint32_t ah3 = *(const uint32_t*)&sAhi[(row + 8) * SROWA + kc + 8];
                #pragma unroll
                for (int nt = 0; nt < 4; nt++) {
                    MMA16816(acc[mt][nt], ah0, ah1, ah2, ah3, bh[nt][0], bh[nt][1]);
                    MMA16816(acc[mt][nt], ah0, ah1, ah2, ah3, bl[nt][0], bl[nt][1]);
                }
                uint32_t al0 = *(const uint32_t*)&sAlo[row * SROWA + kc];
                uint32_t al1 = *(const uint32_t*)&sAlo[(row + 8) * SROWA + kc];
                uint32_t al2 = *(const uint32_t*)&sAlo[row * SROWA + kc + 8];
                uint32_t al3 = *(const uint32_t*)&sAlo[(row + 8) * SROWA + kc + 8];
                #pragma unroll
                for (int nt = 0; nt < 4; nt++) {
                    MMA16816(acc[mt][nt], al0, al1, al2, al3, bh[nt][0], bh[nt][1]);
                }
            }
        }
        __syncthreads();
    }
    #undef FETCH
    #undef STORE

    #pragma unroll
    for (int mt = 0; mt < 2; mt++)
        #pragma unroll
        for (int nt = 0; nt < 4; nt++) {
            int row = m0 + wm0 + mt * 16 + r;
            int col = n0 + wn0 + nt * 8 + c2;
            float2 v0 = make_float2(acc[mt][nt][0], acc[mt][nt][1]);
            float2 v1 = make_float2(acc[mt][nt][2], acc[mt][nt][3]);
            *(float2*)&C[(size_t)row * N + col]       = v0;
            *(float2*)&C[(size_t)(row + 8) * N + col] = v1;
        }
}

// ---------------- 4) windowed causal attention + fused RoPE ---------------
// grid (T/32, B*HEADS), block 256. RoPE applied while loading Q/K smem.
__global__ __launch_bounds__(256)
void attn_kernel() {
    const int t0 = blockIdx.x * 32;
    const int bh = blockIdx.y;
    const int b = bh / HEADS, h = bh % HEADS;

    __shared__ float Qs[32][64];
    __shared__ float Ks[64][65];
    __shared__ float Vs[64][65];

    const int tid = threadIdx.x;
    const float FREQ = 9.210340371976184f / 32.0f;   // ln(10000)/32

    // Q: 32 queries x 32 rotation pairs, rope fused
    for (int i = tid; i < 32 * 32; i += 256) {
        int q = i >> 5, d = i & 31;
        int tpos = t0 + q;
        float inv = expf(-(float)d * FREQ);
        float sn, cs;
        sincosf((float)tpos * inv, &sn, &cs);
        size_t base = ((size_t)(b * TLEN + tpos)) * (3 * DIM) + h * DH + d;
        float v1 = g_qkv[base];
        float v2 = g_qkv[base + 32];
        Qs[q][d]      = v1 * cs - v2 * sn;
        Qs[q][d + 32] = v2 * cs + v1 * sn;
    }
    // K: 63 rows x 32 pairs, rope fused
    for (int i = tid; i < 63 * 32; i += 256) {
        int rr = i >> 5, d = i & 31;
        int kpos = t0 - 31 + rr;
        float k1 = 0.f, k2 = 0.f;
        if (kpos >= 0) {
            float inv = expf(-(float)d * FREQ);
            float sn, cs;
            sincosf((float)kpos * inv, &sn, &cs);
            size_t off = ((size_t)(b * TLEN + kpos)) * (3 * DIM) + DIM + h * DH + d;
            float v1 = g_qkv[off];
            float v2 = g_qkv[off + 32];
            k1 = v1 * cs - v2 * sn;
            k2 = v2 * cs + v1 * sn;
        }
        Ks[rr][d]      = k1;
        Ks[rr][d + 32] = k2;
    }
    // V: plain copy
    for (int i = tid; i < 63 * 64; i += 256) {
        int rr = i >> 6, d = i & 63;
        int kpos = t0 - 31 + rr;
        float vv = 0.f;
        if (kpos >= 0)
            vv = g_qkv[((size_t)(b * TLEN + kpos)) * (3 * DIM) + 2 * DIM + h * DH + d];
        Vs[rr][d] = vv;
    }
    __syncthreads();

    const int warp = tid >> 5, lane = tid & 31;
    #pragma unroll
    for (int j = 0; j < 4; j++) {
        const int ql   = warp * 4 + j;
        const int qpos = t0 + ql;
        const int rr   = ql + lane;
        const int kpos = qpos - 31 + lane;
        const bool valid = (kpos >= 0);

        float s = 0.f;
        #pragma unroll
        for (int d = 0; d < 64; d++) s = fmaf(Qs[ql][d], Ks[rr][d], s);
        s *= 0.125f;
        s = valid ? s : -INFINITY;

        float m = s;
        #pragma unroll
        for (int o = 16; o; o >>= 1) m = fmaxf(m, __shfl_xor_sync(0xffffffffu, m, o));
        float p = valid ? expf(s - m) : 0.f;
        float sum = p;
        #pragma unroll
        for (int o = 16; o; o >>= 1) sum += __shfl_xor_sync(0xffffffffu, sum, o);
        p /= sum;

        float o0 = 0.f, o1 = 0.f;
        #pragma unroll
        for (int jj = 0; jj < 32; jj++) {
            float pj = __shfl_sync(0xffffffffu, p, jj);
            int rj = ql + jj;
            o0 = fmaf(pj, Vs[rj][2 * lane],     o0);
            o1 = fmaf(pj, Vs[rj][2 * lane + 1], o1);
        }
        size_t oo = ((size_t)(b * TLEN + qpos)) * DIM + h * DH + 2 * lane;
        g_att[oo]     = o0;
        g_att[oo + 1] = o1;
    }
}

// ---------------- 6) transpose + residual ----------------------------------
__global__ void add_transpose_kernel(const float* __restrict__ x,
                                     float* __restrict__ out) {
    const int b  = blockIdx.z;
    const int t0 = blockIdx.x * 32, c0 = blockIdx.y * 32;
    const int tx = threadIdx.x, ty = threadIdx.y;
    __shared__ float tile[32][33];
    #pragma unroll
    for (int k = 0; k < 4; k++) {
        int tl = ty + 8 * k;
        tile[tl][tx] = g_proj[((size_t)(b * TLEN + t0 + tl)) * DIM + c0 + tx];
    }
    __syncthreads();
    #pragma unroll
    for (int k = 0; k < 4; k++) {
        int cl = ty + 8 * k;
        size_t idx = ((size_t)b * DIM + c0 + cl) * TLEN + t0 + tx;
        out[idx] = tile[tx][cl] + x[idx];
    }
}

// ---------------- launch ---------------------------------------------------
extern "C" void kernel_launch(void* const* d_in, const int* in_sizes, int n_in,
                              void* d_out, int out_size) {
    const float* x     = (const float*)d_in[0];
    const float* ln_w  = (const float*)d_in[1];
    const float* ln_b  = (const float*)d_in[2];
    const float* w_qkv = (const float*)d_in[3];
    const float* w_out = (const float*)d_in[4];
    float* out = (float*)d_out;

    ln_transpose_kernel<<<dim3(TLEN / 32, BATCH), dim3(32, 8)>>>(x, ln_w, ln_b);

    // QKV GEMM: [4096,1024]x[1024,3072]
    sgemm_tc_kernel<<<dim3((3 * DIM) / 64, NTOK / 128), 256>>>(0, w_qkv, 3 * DIM);

    // attention with fused RoPE
    attn_kernel<<<dim3(TLEN / 32, BATCH * HEADS), 256>>>();

    // out projection: [4096,1024]x[1024,1024]
    sgemm_tc_kernel<<<dim3(DIM / 64, NTOK / 128), 256>>>(1, w_out, DIM);

    add_transpose_kernel<<<dim3(TLEN / 32, DIM / 32, BATCH), dim3(32, 8)>>>(x, out);
}

// round 13
// speedup vs baseline: 1.5529x; 1.5529x over previous
#include <cuda_runtime.h>
#include <cuda_bf16.h>
#include <cstdint>
#include <math.h>

#define BATCH 2
#define TLEN 2048
#define DIM 1024
#define HEADS 16
#define DH 64
#define WINDOW 32
#define NTOK (BATCH * TLEN)
#define LN_EPS 1e-5f

// ---------------- scratch (device globals; 96 MB fp32 set) ----------------
__device__ float g_h[(size_t)NTOK * DIM];          // LN output, [tok, DIM]
__device__ float g_qkv[(size_t)NTOK * 3 * DIM];    // [tok, 3*DIM]
__device__ float g_att[(size_t)NTOK * DIM];        // attention output
__device__ float g_proj[(size_t)NTOK * DIM];       // out-proj result

// ---------------- 1) LayerNorm + transpose [B,C,T] -> [tok,C] -------------
__global__ void ln_transpose_kernel(const float* __restrict__ x,
                                    const float* __restrict__ w,
                                    const float* __restrict__ bias) {
    const int b  = blockIdx.y;
    const int t0 = blockIdx.x * 32;
    const int tx = threadIdx.x, ty = threadIdx.y;
    const float* xb = x + (size_t)b * DIM * TLEN;

    float s = 0.f, ss = 0.f;
    for (int c = ty; c < DIM; c += 8) {
        float v = xb[(size_t)c * TLEN + t0 + tx];
        s += v; ss += v * v;
    }
    __shared__ float rs[8][32], rq[8][32];
    rs[ty][tx] = s; rq[ty][tx] = ss;
    __syncthreads();
    __shared__ float mu[32], rstd[32];
    if (ty == 0) {
        float a = 0.f, q = 0.f;
        #pragma unroll
        for (int i = 0; i < 8; i++) { a += rs[i][tx]; q += rq[i][tx]; }
        float m   = a / (float)DIM;
        float var = q / (float)DIM - m * m;
        mu[tx]   = m;
        rstd[tx] = rsqrtf(var + LN_EPS);
    }
    __syncthreads();

    __shared__ float tile[32][33];
    for (int c0 = 0; c0 < DIM; c0 += 32) {
        #pragma unroll
        for (int k = 0; k < 4; k++) {
            int cl = ty + 8 * k;
            tile[cl][tx] = xb[(size_t)(c0 + cl) * TLEN + t0 + tx];
        }
        __syncthreads();
        #pragma unroll
        for (int k = 0; k < 4; k++) {
            int tl = ty + 8 * k;
            int c  = c0 + tx;
            float v = (tile[tx][tl] - mu[tl]) * rstd[tl] * w[c] + bias[c];
            g_h[((size_t)b * TLEN + t0 + tl) * DIM + c] = v;
        }
        __syncthreads();
    }
}

// ---------------- 2/5) bf16x3 GEMM: presplit smem + ldmatrix --------------
// C[M,N] = A[M,K] * B[K,N]; A [tok,K], B native [K,N] (no pre-transpose).
// CTA tile 128x64xk32, 8 warps (4m x 2n), warp tile 32x32.
// bf16 hi/lo split at tile load (vectorized uint2 STS); fragments via
// ldmatrix.x4 (A) / ldmatrix.x4.trans (B).
#define SRA 40   // bf16 k-stride of A smem rows (80B)
#define SRB 72   // bf16 n-stride of B smem rows (144B)

#define MMA16816(d, a0, a1, a2, a3, b0, b1)                                   \
    asm volatile("mma.sync.aligned.m16n8k16.row.col.f32.bf16.bf16.f32 "      \
                 "{%0,%1,%2,%3}, {%4,%5,%6,%7}, {%8,%9}, {%0,%1,%2,%3};"     \
                 : "+f"(d[0]), "+f"(d[1]), "+f"(d[2]), "+f"(d[3])             \
                 : "r"(a0), "r"(a1), "r"(a2), "r"(a3), "r"(b0), "r"(b1))

#define LDSM4(r0, r1, r2, r3, addr)                                           \
    asm volatile("ldmatrix.sync.aligned.m8n8.x4.shared.b16 {%0,%1,%2,%3}, [%4];" \
                 : "=r"(r0), "=r"(r1), "=r"(r2), "=r"(r3) : "r"(addr))

#define LDSM4T(r0, r1, r2, r3, addr)                                          \
    asm volatile("ldmatrix.sync.aligned.m8n8.x4.trans.shared.b16 {%0,%1,%2,%3}, [%4];" \
                 : "=r"(r0), "=r"(r1), "=r"(r2), "=r"(r3) : "r"(addr))

__device__ __forceinline__ void split2(float fx, float fy,
                                       uint32_t& hi, uint32_t& lo) {
    __nv_bfloat162 h = __floats2bfloat162_rn(fx, fy);
    float2 hf = __bfloat1622float2(h);
    __nv_bfloat162 l = __floats2bfloat162_rn(fx - hf.x, fy - hf.y);
    hi = *(uint32_t*)&h;
    lo = *(uint32_t*)&l;
}

__global__ __launch_bounds__(256)
void sgemm_tc_kernel(int which, const float* __restrict__ Bm, int N) {
    const float* __restrict__ A = (which == 0) ? g_h : g_att;
    float* __restrict__ C = (which == 0) ? g_qkv : g_proj;
    const int K = DIM;

    __shared__ __nv_bfloat16 sAhi[128 * SRA];   // 10240 B
    __shared__ __nv_bfloat16 sAlo[128 * SRA];
    __shared__ __nv_bfloat16 sBhi[32 * SRB];    //  4608 B
    __shared__ __nv_bfloat16 sBlo[32 * SRB];    // total 29696 B

    const int tid  = threadIdx.x;
    const int warp = tid >> 5, lane = tid & 31;
    const int wm0 = (warp & 3) * 32;
    const int wn0 = (warp >> 2) * 32;
    const int m0 = blockIdx.y * 128;
    const int n0 = blockIdx.x * 64;

    float acc[2][4][4];
    #pragma unroll
    for (int i = 0; i < 2; i++)
        #pragma unroll
        for (int j = 0; j < 4; j++)
            #pragma unroll
            for (int k = 0; k < 4; k++) acc[i][j][k] = 0.f;

    // ldmatrix lane addressing
    const int g8 = lane >> 3;     // matrix index 0..3
    const int lr = lane & 7;      // row within matrix
    const uint32_t uAhi = (uint32_t)__cvta_generic_to_shared(sAhi);
    const uint32_t uAlo = (uint32_t)__cvta_generic_to_shared(sAlo);
    const uint32_t uBhi = (uint32_t)__cvta_generic_to_shared(sBhi);
    const uint32_t uBlo = (uint32_t)__cvta_generic_to_shared(sBlo);
    // A x4: matrices (row: +0/+8 via g8&1, k: +0/+8 via g8>>1)
    const uint32_t aOff = (uint32_t)(((wm0 + (g8 & 1) * 8 + lr) * SRA + (g8 >> 1) * 8) * 2);
    // B x4.trans: matrices (k: +0/+8 via g8&1, n: +0/+8 via g8>>1)
    const uint32_t bOff = (uint32_t)((((g8 & 1) * 8 + lr) * SRB + wn0 + (g8 >> 1) * 8) * 2);

    // loader mapping: A 4 float4/thread, B 2 float4/thread
    const int ar = tid >> 3;             // 0..31 (+32*i)
    const int ac = (tid & 7) * 4;        // k col 0..28
    const int br = tid >> 4;             // 0..15 (+16*i)  (k row)
    const int bc = (tid & 15) * 4;       // n col 0..60

    float4 pa[4], pb[2];

    #define FETCH(kt)                                                          \
    do {                                                                       \
        int kb = (kt) * 32;                                                    \
        _Pragma("unroll")                                                      \
        for (int i = 0; i < 4; i++)                                            \
            pa[i] = *(const float4*)&A[(size_t)(m0 + ar + 32 * i) * K + kb + ac]; \
        _Pragma("unroll")                                                      \
        for (int i = 0; i < 2; i++)                                            \
            pb[i] = *(const float4*)&Bm[(size_t)(kb + br + 16 * i) * N + n0 + bc]; \
    } while (0)

    #define STORE()                                                            \
    do {                                                                       \
        _Pragma("unroll")                                                      \
        for (int i = 0; i < 4; i++) {                                          \
            int row = ar + 32 * i;                                             \
            uint32_t h0, l0, h1, l1;                                           \
            split2(pa[i].x, pa[i].y, h0, l0);                                  \
            split2(pa[i].z, pa[i].w, h1, l1);                                  \
            *(uint2*)&sAhi[row * SRA + ac] = make_uint2(h0, h1);               \
            *(uint2*)&sAlo[row * SRA + ac] = make_uint2(l0, l1);               \
        }                                                                      \
        _Pragma("unroll")                                                      \
        for (int i = 0; i < 2; i++) {                                          \
            int krow = br + 16 * i;                                            \
            uint32_t h0, l0, h1, l1;                                           \
            split2(pb[i].x, pb[i].y, h0, l0);                                  \
            split2(pb[i].z, pb[i].w, h1, l1);                                  \
            *(uint2*)&sBhi[krow * SRB + bc] = make_uint2(h0, h1);              \
            *(uint2*)&sBlo[krow * SRB + bc] = make_uint2(l0, l1);              \
        }                                                                      \
    } while (0)

    const int ntiles = K / 32;
    FETCH(0);

    for (int kt = 0; kt < ntiles; kt++) {
        STORE();
        __syncthreads();
        if (kt + 1 < ntiles) FETCH(kt + 1);   // overlap next tile's GMEM loads

        #pragma unroll
        for (int ks = 0; ks < 2; ks++) {
            // B fragments: 2 x4.trans per hi/lo cover all 4 n-groups
            uint32_t bh[4][2], bl[4][2];
            #pragma unroll
            for (int p = 0; p < 2; p++) {
                uint32_t ba = bOff + (uint32_t)(p * 32 + ks * 16 * SRB * 2);
                LDSM4T(bh[2 * p][0], bh[2 * p][1], bh[2 * p + 1][0], bh[2 * p + 1][1], uBhi + ba);
                LDSM4T(bl[2 * p][0], bl[2 * p][1], bl[2 * p + 1][0], bl[2 * p + 1][1], uBlo + ba);
            }
            #pragma unroll
            for (int mt = 0; mt < 2; mt++) {
                uint32_t aa = aOff + (uint32_t)(mt * 16 * SRA * 2 + ks * 32);
                uint32_t a0, a1, a2, a3, l0, l1, l2, l3;
                LDSM4(a0, a1, a2, a3, uAhi + aa);
                LDSM4(l0, l1, l2, l3, uAlo + aa);
                #pragma unroll
                for (int nt = 0; nt < 4; nt++) {
                    MMA16816(acc[mt][nt], a0, a1, a2, a3, bh[nt][0], bh[nt][1]);
                    MMA16816(acc[mt][nt], a0, a1, a2, a3, bl[nt][0], bl[nt][1]);
                    MMA16816(acc[mt][nt], l0, l1, l2, l3, bh[nt][0], bh[nt][1]);
                }
            }
        }
        __syncthreads();
    }
    #undef FETCH
    #undef STORE

    const int r  = lane >> 2;
    const int c2 = (lane & 3) * 2;
    #pragma unroll
    for (int mt = 0; mt < 2; mt++)
        #pragma unroll
        for (int nt = 0; nt < 4; nt++) {
            int row = m0 + wm0 + mt * 16 + r;
            int col = n0 + wn0 + nt * 8 + c2;
            float2 v0 = make_float2(acc[mt][nt][0], acc[mt][nt][1]);
            float2 v1 = make_float2(acc[mt][nt][2], acc[mt][nt][3]);
            *(float2*)&C[(size_t)row * N + col]       = v0;
            *(float2*)&C[(size_t)(row + 8) * N + col] = v1;
        }
}

// ---------------- 4) windowed causal attention + fused RoPE ---------------
__global__ __launch_bounds__(256)
void attn_kernel() {
    const int t0 = blockIdx.x * 32;
    const int bh = blockIdx.y;
    const int b = bh / HEADS, h = bh % HEADS;

    __shared__ float Qs[32][64];
    __shared__ float Ks[64][65];
    __shared__ float Vs[64][65];

    const int tid = threadIdx.x;
    const float FREQ = 9.210340371976184f / 32.0f;   // ln(10000)/32

    for (int i = tid; i < 32 * 32; i += 256) {
        int q = i >> 5, d = i & 31;
        int tpos = t0 + q;
        float inv = expf(-(float)d * FREQ);
        float sn, cs;
        sincosf((float)tpos * inv, &sn, &cs);
        size_t base = ((size_t)(b * TLEN + tpos)) * (3 * DIM) + h * DH + d;
        float v1 = g_qkv[base];
        float v2 = g_qkv[base + 32];
        Qs[q][d]      = v1 * cs - v2 * sn;
        Qs[q][d + 32] = v2 * cs + v1 * sn;
    }
    for (int i = tid; i < 63 * 32; i += 256) {
        int rr = i >> 5, d = i & 31;
        int kpos = t0 - 31 + rr;
        float k1 = 0.f, k2 = 0.f;
        if (kpos >= 0) {
            float inv = expf(-(float)d * FREQ);
            float sn, cs;
            sincosf((float)kpos * inv, &sn, &cs);
            size_t off = ((size_t)(b * TLEN + kpos)) * (3 * DIM) + DIM + h * DH + d;
            float v1 = g_qkv[off];
            float v2 = g_qkv[off + 32];
            k1 = v1 * cs - v2 * sn;
            k2 = v2 * cs + v1 * sn;
        }
        Ks[rr][d]      = k1;
        Ks[rr][d + 32] = k2;
    }
    for (int i = tid; i < 63 * 64; i += 256) {
        int rr = i >> 6, d = i & 63;
        int kpos = t0 - 31 + rr;
        float vv = 0.f;
        if (kpos >= 0)
            vv = g_qkv[((size_t)(b * TLEN + kpos)) * (3 * DIM) + 2 * DIM + h * DH + d];
        Vs[rr][d] = vv;
    }
    __syncthreads();

    const int warp = tid >> 5, lane = tid & 31;
    #pragma unroll
    for (int j = 0; j < 4; j++) {
        const int ql   = warp * 4 + j;
        const int qpos = t0 + ql;
        const int rr   = ql + lane;
        const int kpos = qpos - 31 + lane;
        const bool valid = (kpos >= 0);

        float s = 0.f;
        #pragma unroll
        for (int d = 0; d < 64; d++) s = fmaf(Qs[ql][d], Ks[rr][d], s);
        s *= 0.125f;
        s = valid ? s : -INFINITY;

        float m = s;
        #pragma unroll
        for (int o = 16; o; o >>= 1) m = fmaxf(m, __shfl_xor_sync(0xffffffffu, m, o));
        float p = valid ? expf(s - m) : 0.f;
        float sum = p;
        #pragma unroll
        for (int o = 16; o; o >>= 1) sum += __shfl_xor_sync(0xffffffffu, sum, o);
        p /= sum;

        float o0 = 0.f, o1 = 0.f;
        #pragma unroll
        for (int jj = 0; jj < 32; jj++) {
            float pj = __shfl_sync(0xffffffffu, p, jj);
            int rj = ql + jj;
            o0 = fmaf(pj, Vs[rj][2 * lane],     o0);
            o1 = fmaf(pj, Vs[rj][2 * lane + 1], o1);
        }
        size_t oo = ((size_t)(b * TLEN + qpos)) * DIM + h * DH + 2 * lane;
        g_att[oo]     = o0;
        g_att[oo + 1] = o1;
    }
}

// ---------------- 6) transpose + residual ----------------------------------
__global__ void add_transpose_kernel(const float* __restrict__ x,
                                     float* __restrict__ out) {
    const int b  = blockIdx.z;
    const int t0 = blockIdx.x * 32, c0 = blockIdx.y * 32;
    const int tx = threadIdx.x, ty = threadIdx.y;
    __shared__ float tile[32][33];
    #pragma unroll
    for (int k = 0; k < 4; k++) {
        int tl = ty + 8 * k;
        tile[tl][tx] = g_proj[((size_t)(b * TLEN + t0 + tl)) * DIM + c0 + tx];
    }
    __syncthreads();
    #pragma unroll
    for (int k = 0; k < 4; k++) {
        int cl = ty + 8 * k;
        size_t idx = ((size_t)b * DIM + c0 + cl) * TLEN + t0 + tx;
        out[idx] = tile[tx][cl] + x[idx];
    }
}

// ---------------- launch ---------------------------------------------------
extern "C" void kernel_launch(void* const* d_in, const int* in_sizes, int n_in,
                              void* d_out, int out_size) {
    const float* x     = (const float*)d_in[0];
    const float* ln_w  = (const float*)d_in[1];
    const float* ln_b  = (const float*)d_in[2];
    const float* w_qkv = (const float*)d_in[3];
    const float* w_out = (const float*)d_in[4];
    float* out = (float*)d_out;

    ln_transpose_kernel<<<dim3(TLEN / 32, BATCH), dim3(32, 8)>>>(x, ln_w, ln_b);

    // QKV GEMM: [4096,1024] x [1024,3072] -> g_qkv
    sgemm_tc_kernel<<<dim3((3 * DIM) / 64, NTOK / 128), 256>>>(0, w_qkv, 3 * DIM);

    // attention with fused RoPE -> g_att
    attn_kernel<<<dim3(TLEN / 32, BATCH * HEADS), 256>>>();

    // out projection: [4096,1024] x [1024,1024] -> g_proj
    sgemm_tc_kernel<<<dim3(DIM / 64, NTOK / 128), 256>>>(1, w_out, DIM);

    add_transpose_kernel<<<dim3(TLEN / 32, DIM / 32, BATCH), dim3(32, 8)>>>(x, out);
}

// round 14
// speedup vs baseline: 1.5539x; 1.0007x over previous
#include <cuda_runtime.h>
#include <cuda_bf16.h>
#include <cstdint>
#include <math.h>

#define BATCH 2
#define TLEN 2048
#define DIM 1024
#define HEADS 16
#define DH 64
#define WINDOW 32
#define NTOK (BATCH * TLEN)
#define LN_EPS 1e-5f

// ---------------- scratch (device globals; 96 MB fp32 set) ----------------
__device__ float g_h[(size_t)NTOK * DIM];          // LN output, [tok, DIM]
__device__ float g_qkv[(size_t)NTOK * 3 * DIM];    // [tok, 3*DIM]
__device__ float g_att[(size_t)NTOK * DIM];        // attention output
__device__ float g_proj[(size_t)NTOK * DIM];       // out-proj result

// ---------------- 1) LayerNorm + transpose [B,C,T] -> [tok,C] -------------
__global__ void ln_transpose_kernel(const float* __restrict__ x,
                                    const float* __restrict__ w,
                                    const float* __restrict__ bias) {
    const int b  = blockIdx.y;
    const int t0 = blockIdx.x * 32;
    const int tx = threadIdx.x, ty = threadIdx.y;
    const float* xb = x + (size_t)b * DIM * TLEN;

    float s = 0.f, ss = 0.f;
    for (int c = ty; c < DIM; c += 8) {
        float v = xb[(size_t)c * TLEN + t0 + tx];
        s += v; ss += v * v;
    }
    __shared__ float rs[8][32], rq[8][32];
    rs[ty][tx] = s; rq[ty][tx] = ss;
    __syncthreads();
    __shared__ float mu[32], rstd[32];
    if (ty == 0) {
        float a = 0.f, q = 0.f;
        #pragma unroll
        for (int i = 0; i < 8; i++) { a += rs[i][tx]; q += rq[i][tx]; }
        float m   = a / (float)DIM;
        float var = q / (float)DIM - m * m;
        mu[tx]   = m;
        rstd[tx] = rsqrtf(var + LN_EPS);
    }
    __syncthreads();

    __shared__ float tile[32][33];
    for (int c0 = 0; c0 < DIM; c0 += 32) {
        #pragma unroll
        for (int k = 0; k < 4; k++) {
            int cl = ty + 8 * k;
            tile[cl][tx] = xb[(size_t)(c0 + cl) * TLEN + t0 + tx];
        }
        __syncthreads();
        #pragma unroll
        for (int k = 0; k < 4; k++) {
            int tl = ty + 8 * k;
            int c  = c0 + tx;
            float v = (tile[tx][tl] - mu[tl]) * rstd[tl] * w[c] + bias[c];
            g_h[((size_t)b * TLEN + t0 + tl) * DIM + c] = v;
        }
        __syncthreads();
    }
}

// ---------------- 2/5) bf16x3 GEMM: presplit smem + ldmatrix + swizzle ----
// C[M,N] = A[M,K] * B[K,N]; A [tok,K], B native [K,N].
// CTA tile 128x64xk32, 8 warps (4m x 2n), warp tile 32x32.
// XOR-8 swizzle on both tiles kills the row/row+8 LDSM bank conflict.
#define SRA 40   // bf16 k-stride of A smem rows (80B)
#define SRB 72   // bf16 n-stride of B smem rows (144B)

#define MMA16816(d, a0, a1, a2, a3, b0, b1)                                   \
    asm volatile("mma.sync.aligned.m16n8k16.row.col.f32.bf16.bf16.f32 "      \
                 "{%0,%1,%2,%3}, {%4,%5,%6,%7}, {%8,%9}, {%0,%1,%2,%3};"     \
                 : "+f"(d[0]), "+f"(d[1]), "+f"(d[2]), "+f"(d[3])             \
                 : "r"(a0), "r"(a1), "r"(a2), "r"(a3), "r"(b0), "r"(b1))

#define LDSM4(r0, r1, r2, r3, addr)                                           \
    asm volatile("ldmatrix.sync.aligned.m8n8.x4.shared.b16 {%0,%1,%2,%3}, [%4];" \
                 : "=r"(r0), "=r"(r1), "=r"(r2), "=r"(r3) : "r"(addr))

#define LDSM4T(r0, r1, r2, r3, addr)                                          \
    asm volatile("ldmatrix.sync.aligned.m8n8.x4.trans.shared.b16 {%0,%1,%2,%3}, [%4];" \
                 : "=r"(r0), "=r"(r1), "=r"(r2), "=r"(r3) : "r"(addr))

__device__ __forceinline__ void split2(float fx, float fy,
                                       uint32_t& hi, uint32_t& lo) {
    __nv_bfloat162 h = __floats2bfloat162_rn(fx, fy);
    float2 hf = __bfloat1622float2(h);
    __nv_bfloat162 l = __floats2bfloat162_rn(fx - hf.x, fy - hf.y);
    hi = *(uint32_t*)&h;
    lo = *(uint32_t*)&l;
}

__global__ __launch_bounds__(256)
void sgemm_tc_kernel(int which, const float* __restrict__ Bm, int N) {
    const float* __restrict__ A = (which == 0) ? g_h : g_att;
    float* __restrict__ C = (which == 0) ? g_qkv : g_proj;
    const int K = DIM;

    __shared__ __nv_bfloat16 sAhi[128 * SRA];   // 10240 B
    __shared__ __nv_bfloat16 sAlo[128 * SRA];
    __shared__ __nv_bfloat16 sBhi[32 * SRB];    //  4608 B
    __shared__ __nv_bfloat16 sBlo[32 * SRB];    // total 29696 B

    const int tid  = threadIdx.x;
    const int warp = tid >> 5, lane = tid & 31;
    const int wm0 = (warp & 3) * 32;
    const int wn0 = (warp >> 2) * 32;
    const int m0 = blockIdx.y * 128;
    const int n0 = blockIdx.x * 64;

    float acc[2][4][4];
    #pragma unroll
    for (int i = 0; i < 2; i++)
        #pragma unroll
        for (int j = 0; j < 4; j++)
            #pragma unroll
            for (int k = 0; k < 4; k++) acc[i][j][k] = 0.f;

    // ldmatrix lane addressing (with XOR-8 swizzle matching the stores)
    const int g8 = lane >> 3;     // matrix index 0..3
    const int lr = lane & 7;      // row within matrix
    const int xo = (g8 & 1) * 8;  // 8-group parity XOR term (elements)
    const uint32_t uAhi = (uint32_t)__cvta_generic_to_shared(sAhi);
    const uint32_t uAlo = (uint32_t)__cvta_generic_to_shared(sAlo);
    const uint32_t uBhi = (uint32_t)__cvta_generic_to_shared(sBhi);
    const uint32_t uBlo = (uint32_t)__cvta_generic_to_shared(sBlo);
    // A x4: row = wm0 + (g8&1)*8 + lr (+16*mt), col = (g8>>1)*8 (+16*ks); col ^= xo
    const int aRow = wm0 + (g8 & 1) * 8 + lr;
    const int aCol0 = (g8 >> 1) * 8;
    // B x4.trans: krow = (g8&1)*8 + lr (+16*ks), col = wn0 + (g8>>1)*8; col ^= xo
    const int bRow = (g8 & 1) * 8 + lr;
    const int bCol = (wn0 + (g8 >> 1) * 8) ^ xo;

    // loader mapping: A 4 float4/thread, B 2 float4/thread
    const int ar = tid >> 3;             // 0..31 (+32*i)
    const int ac = (tid & 7) * 4;        // k col 0..28
    const int br = tid >> 4;             // 0..15 (+16*i)  (k row)
    const int bc = (tid & 15) * 4;       // n col 0..60

    float4 pa[4], pb[2];

    #define FETCH(kt)                                                          \
    do {                                                                       \
        int kb = (kt) * 32;                                                    \
        _Pragma("unroll")                                                      \
        for (int i = 0; i < 4; i++)                                            \
            pa[i] = *(const float4*)&A[(size_t)(m0 + ar + 32 * i) * K + kb + ac]; \
        _Pragma("unroll")                                                      \
        for (int i = 0; i < 2; i++)                                            \
            pb[i] = *(const float4*)&Bm[(size_t)(kb + br + 16 * i) * N + n0 + bc]; \
    } while (0)

    #define STORE()                                                            \
    do {                                                                       \
        _Pragma("unroll")                                                      \
        for (int i = 0; i < 4; i++) {                                          \
            int row = ar + 32 * i;                                             \
            int col = ac ^ (((row >> 3) & 1) * 8);                             \
            uint32_t h0, l0, h1, l1;                                           \
            split2(pa[i].x, pa[i].y, h0, l0);                                  \
            split2(pa[i].z, pa[i].w, h1, l1);                                  \
            *(uint2*)&sAhi[row * SRA + col] = make_uint2(h0, h1);              \
            *(uint2*)&sAlo[row * SRA + col] = make_uint2(l0, l1);              \
        }                                                                      \
        _Pragma("unroll")                                                      \
        for (int i = 0; i < 2; i++) {                                          \
            int krow = br + 16 * i;                                            \
            int col = bc ^ (((krow >> 3) & 1) * 8);                            \
            uint32_t h0, l0, h1, l1;                                           \
            split2(pb[i].x, pb[i].y, h0, l0);                                  \
            split2(pb[i].z, pb[i].w, h1, l1);                                  \
            *(uint2*)&sBhi[krow * SRB + col] = make_uint2(h0, h1);             \
            *(uint2*)&sBlo[krow * SRB + col] = make_uint2(l0, l1);             \
        }                                                                      \
    } while (0)

    const int ntiles = K / 32;
    FETCH(0);

    for (int kt = 0; kt < ntiles; kt++) {
        STORE();
        __syncthreads();
        if (kt + 1 < ntiles) FETCH(kt + 1);   // overlap next tile's GMEM loads

        #pragma unroll
        for (int ks = 0; ks < 2; ks++) {
            // B fragments: krow group parity is g8&1 -> col XOR already in bCol
            uint32_t bh[4][2], bl[4][2];
            #pragma unroll
            for (int p = 0; p < 2; p++) {
                uint32_t ba = (uint32_t)(((bRow + ks * 16) * SRB + bCol + p * 16) * 2);
                LDSM4T(bh[2 * p][0], bh[2 * p][1], bh[2 * p + 1][0], bh[2 * p + 1][1], uBhi + ba);
                LDSM4T(bl[2 * p][0], bl[2 * p][1], bl[2 * p + 1][0], bl[2 * p + 1][1], uBlo + ba);
            }
            #pragma unroll
            for (int mt = 0; mt < 2; mt++) {
                uint32_t aa = (uint32_t)(((aRow + mt * 16) * SRA + ((aCol0 + ks * 16) ^ xo)) * 2);
                uint32_t a0, a1, a2, a3, l0, l1, l2, l3;
                LDSM4(a0, a1, a2, a3, uAhi + aa);
                LDSM4(l0, l1, l2, l3, uAlo + aa);
                #pragma unroll
                for (int nt = 0; nt < 4; nt++) {
                    MMA16816(acc[mt][nt], a0, a1, a2, a3, bh[nt][0], bh[nt][1]);
                    MMA16816(acc[mt][nt], a0, a1, a2, a3, bl[nt][0], bl[nt][1]);
                    MMA16816(acc[mt][nt], l0, l1, l2, l3, bh[nt][0], bh[nt][1]);
                }
            }
        }
        __syncthreads();
    }
    #undef FETCH
    #undef STORE

    const int r  = lane >> 2;
    const int c2 = (lane & 3) * 2;
    #pragma unroll
    for (int mt = 0; mt < 2; mt++)
        #pragma unroll
        for (int nt = 0; nt < 4; nt++) {
            int row = m0 + wm0 + mt * 16 + r;
            int col = n0 + wn0 + nt * 8 + c2;
            float2 v0 = make_float2(acc[mt][nt][0], acc[mt][nt][1]);
            float2 v1 = make_float2(acc[mt][nt][2], acc[mt][nt][3]);
            *(float2*)&C[(size_t)row * N + col]       = v0;
            *(float2*)&C[(size_t)(row + 8) * N + col] = v1;
        }
}

// ---------------- 4) windowed causal attention + fused RoPE ---------------
__global__ __launch_bounds__(256)
void attn_kernel() {
    const int t0 = blockIdx.x * 32;
    const int bh = blockIdx.y;
    const int b = bh / HEADS, h = bh % HEADS;

    __shared__ float Qs[32][64];
    __shared__ float Ks[64][65];
    __shared__ float Vs[64][65];

    const int tid = threadIdx.x;
    const float FREQ = 9.210340371976184f / 32.0f;   // ln(10000)/32

    for (int i = tid; i < 32 * 32; i += 256) {
        int q = i >> 5, d = i & 31;
        int tpos = t0 + q;
        float inv = expf(-(float)d * FREQ);
        float sn, cs;
        sincosf((float)tpos * inv, &sn, &cs);
        size_t base = ((size_t)(b * TLEN + tpos)) * (3 * DIM) + h * DH + d;
        float v1 = g_qkv[base];
        float v2 = g_qkv[base + 32];
        Qs[q][d]      = v1 * cs - v2 * sn;
        Qs[q][d + 32] = v2 * cs + v1 * sn;
    }
    for (int i = tid; i < 63 * 32; i += 256) {
        int rr = i >> 5, d = i & 31;
        int kpos = t0 - 31 + rr;
        float k1 = 0.f, k2 = 0.f;
        if (kpos >= 0) {
            float inv = expf(-(float)d * FREQ);
            float sn, cs;
            sincosf((float)kpos * inv, &sn, &cs);
            size_t off = ((size_t)(b * TLEN + kpos)) * (3 * DIM) + DIM + h * DH + d;
            float v1 = g_qkv[off];
            float v2 = g_qkv[off + 32];
            k1 = v1 * cs - v2 * sn;
            k2 = v2 * cs + v1 * sn;
        }
        Ks[rr][d]      = k1;
        Ks[rr][d + 32] = k2;
    }
    for (int i = tid; i < 63 * 64; i += 256) {
        int rr = i >> 6, d = i & 63;
        int kpos = t0 - 31 + rr;
        float vv = 0.f;
        if (kpos >= 0)
            vv = g_qkv[((size_t)(b * TLEN + kpos)) * (3 * DIM) + 2 * DIM + h * DH + d];
        Vs[rr][d] = vv;
    }
    __syncthreads();

    const int warp = tid >> 5, lane = tid & 31;
    #pragma unroll
    for (int j = 0; j < 4; j++) {
        const int ql   = warp * 4 + j;
        const int qpos = t0 + ql;
        const int rr   = ql + lane;
        const int kpos = qpos - 31 + lane;
        const bool valid = (kpos >= 0);

        float s = 0.f;
        #pragma unroll
        for (int d = 0; d < 64; d++) s = fmaf(Qs[ql][d], Ks[rr][d], s);
        s *= 0.125f;
        s = valid ? s : -INFINITY;

        float m = s;
        #pragma unroll
        for (int o = 16; o; o >>= 1) m = fmaxf(m, __shfl_xor_sync(0xffffffffu, m, o));
        float p = valid ? expf(s - m) : 0.f;
        float sum = p;
        #pragma unroll
        for (int o = 16; o; o >>= 1) sum += __shfl_xor_sync(0xffffffffu, sum, o);
        p /= sum;

        float o0 = 0.f, o1 = 0.f;
        #pragma unroll
        for (int jj = 0; jj < 32; jj++) {
            float pj = __shfl_sync(0xffffffffu, p, jj);
            int rj = ql + jj;
            o0 = fmaf(pj, Vs[rj][2 * lane],     o0);
            o1 = fmaf(pj, Vs[rj][2 * lane + 1], o1);
        }
        size_t oo = ((size_t)(b * TLEN + qpos)) * DIM + h * DH + 2 * lane;
        g_att[oo]     = o0;
        g_att[oo + 1] = o1;
    }
}

// ---------------- 6) transpose + residual ----------------------------------
__global__ void add_transpose_kernel(const float* __restrict__ x,
                                     float* __restrict__ out) {
    const int b  = blockIdx.z;
    const int t0 = blockIdx.x * 32, c0 = blockIdx.y * 32;
    const int tx = threadIdx.x, ty = threadIdx.y;
    __shared__ float tile[32][33];
    #pragma unroll
    for (int k = 0; k < 4; k++) {
        int tl = ty + 8 * k;
        tile[tl][tx] = g_proj[((size_t)(b * TLEN + t0 + tl)) * DIM + c0 + tx];
    }
    __syncthreads();
    #pragma unroll
    for (int k = 0; k < 4; k++) {
        int cl = ty + 8 * k;
        size_t idx = ((size_t)b * DIM + c0 + cl) * TLEN + t0 + tx;
        out[idx] = tile[tx][cl] + x[idx];
    }
}

// ---------------- launch ---------------------------------------------------
extern "C" void kernel_launch(void* const* d_in, const int* in_sizes, int n_in,
                              void* d_out, int out_size) {
    const float* x     = (const float*)d_in[0];
    const float* ln_w  = (const float*)d_in[1];
    const float* ln_b  = (const float*)d_in[2];
    const float* w_qkv = (const float*)d_in[3];
    const float* w_out = (const float*)d_in[4];
    float* out = (float*)d_out;

    ln_transpose_kernel<<<dim3(TLEN / 32, BATCH), dim3(32, 8)>>>(x, ln_w, ln_b);

    // QKV GEMM: [4096,1024] x [1024,3072] -> g_qkv
    sgemm_tc_kernel<<<dim3((3 * DIM) / 64, NTOK / 128), 256>>>(0, w_qkv, 3 * DIM);

    // attention with fused RoPE -> g_att
    attn_kernel<<<dim3(TLEN / 32, BATCH * HEADS), 256>>>();

    // out projection: [4096,1024] x [1024,1024] -> g_proj
    sgemm_tc_kernel<<<dim3(DIM / 64, NTOK / 128), 256>>>(1, w_out, DIM);

    add_transpose_kernel<<<dim3(TLEN / 32, DIM / 32, BATCH), dim3(32, 8)>>>(x, out);
}